// round 7
// baseline (speedup 1.0000x reference)
#include <cuda_runtime.h>
#include <cuda_bf16.h>
#include <cstdint>
#include <mma.h>

using namespace nvcuda;

#define N_NODES 100000
#define N_EDGES 3200000
#define NFEAT 1433
#define NHID 40
#define NCLASS 7
#define NC_PAD 8   // padded class dim for vectorized reds

// ---------------- scratch (device globals; no allocations allowed) -------------
__device__ __align__(16) float g_support1[N_NODES * NHID];   // x @ W1
__device__ __align__(16) float g_agg1[N_NODES * NHID];       // scatter target 1
__device__ __align__(16) float g_support2[N_NODES * NC_PAD]; // h @ W2 (padded)
__device__ __align__(16) float g_agg2[N_NODES * NC_PAD];     // scatter target 2

// vector fp32 reduction (sm_90+): one RED.128 instead of 4 scalar REDs
__device__ __forceinline__ void red_add_v4(float* addr, float4 v) {
    asm volatile("red.global.add.v4.f32 [%0], {%1, %2, %3, %4};"
                 :: "l"(addr), "f"(v.x), "f"(v.y), "f"(v.z), "f"(v.w)
                 : "memory");
}

// ================== GEMM1 via wmma bf16 HMMA (split-bf16, 3-term) ==============
// support1[N,40] = x[N,1433] @ W1[1433,40]
// x = xh + xl (bf16 pair), W = wh + wl (bf16 pair)
// acc += xh@wh + xh@wl + xl@wh     (xl@wl dropped: ~2^-18 relative)
// Block: 256 thr (8 warps), tile 128 rows x 48 cols (40 used), KC=64.

#define G1_KC 64
#define G1_NPAD 48
#define G1_ROWS 128

// static smem carve: sxh 16384 | sxl 16384 | swh 6144 | swl 6144 = 45056 B
#define OFF_SXL 16384
#define OFF_SWH 32768
#define OFF_SWL 39936        // note: keep 1024-multiples not required for wmma
#define SMEM_BYTES 46080

__global__ __launch_bounds__(256) void gemm1_wmma_kernel(const float* __restrict__ x,
                                                         const float* __restrict__ W1) {
    __shared__ __align__(16) unsigned char smem_raw[SMEM_BYTES];
    __nv_bfloat16* sxh = reinterpret_cast<__nv_bfloat16*>(smem_raw);
    __nv_bfloat16* sxl = reinterpret_cast<__nv_bfloat16*>(smem_raw + OFF_SXL);
    __nv_bfloat16* swh = reinterpret_cast<__nv_bfloat16*>(smem_raw + OFF_SWH);
    __nv_bfloat16* swl = reinterpret_cast<__nv_bfloat16*>(smem_raw + OFF_SWL);

    const int tid = threadIdx.x;
    const int wid = tid >> 5;
    const int row0 = blockIdx.x * G1_ROWS;

    wmma::fragment<wmma::accumulator, 16, 16, 16, float> acc[3];
#pragma unroll
    for (int t = 0; t < 3; t++) wmma::fill_fragment(acc[t], 0.0f);

    for (int kb = 0; kb < NFEAT; kb += G1_KC) {
        __syncthreads();   // previous iteration's fragment reads done before refill

        // ---- x tile: 128 rows x 64 k (coalesced within row), hi/lo split
#pragma unroll
        for (int i = 0; i < 32; i++) {
            int idx = tid + i * 256;
            int r = idx >> 6;
            int c = idx & 63;
            int gr = row0 + r;
            int gk = kb + c;
            float v = (gr < N_NODES && gk < NFEAT) ? __ldg(&x[(size_t)gr * NFEAT + gk]) : 0.f;
            __nv_bfloat16 h = __float2bfloat16(v);
            __nv_bfloat16 l = __float2bfloat16(v - __bfloat162float(h));
            sxh[r * G1_KC + c] = h;
            sxl[r * G1_KC + c] = l;
        }
        // ---- W tile: 64 k x 48 n (cols 40..47 zero), hi/lo split
#pragma unroll
        for (int i = 0; i < 12; i++) {
            int idx = tid + i * 256;
            int kk = idx / G1_NPAD;
            int nn = idx - kk * G1_NPAD;
            int gk = kb + kk;
            float v = (gk < NFEAT && nn < NHID) ? __ldg(&W1[gk * NHID + nn]) : 0.f;
            __nv_bfloat16 h = __float2bfloat16(v);
            __nv_bfloat16 l = __float2bfloat16(v - __bfloat162float(h));
            swh[kk * G1_NPAD + nn] = h;
            swl[kk * G1_NPAD + nn] = l;
        }
        __syncthreads();

#pragma unroll
        for (int ks = 0; ks < G1_KC / 16; ks++) {
            wmma::fragment<wmma::matrix_a, 16, 16, 16, __nv_bfloat16, wmma::row_major> ah, al;
            wmma::load_matrix_sync(ah, sxh + (wid * 16) * G1_KC + ks * 16, G1_KC);
            wmma::load_matrix_sync(al, sxl + (wid * 16) * G1_KC + ks * 16, G1_KC);
#pragma unroll
            for (int nt = 0; nt < 3; nt++) {
                wmma::fragment<wmma::matrix_b, 16, 16, 16, __nv_bfloat16, wmma::row_major> bh, bl;
                wmma::load_matrix_sync(bh, swh + (ks * 16) * G1_NPAD + nt * 16, G1_NPAD);
                wmma::load_matrix_sync(bl, swl + (ks * 16) * G1_NPAD + nt * 16, G1_NPAD);
                wmma::mma_sync(acc[nt], ah, bh, acc[nt]);
                wmma::mma_sync(acc[nt], ah, bl, acc[nt]);
                wmma::mma_sync(acc[nt], al, bh, acc[nt]);
            }
        }
    }

    // epilogue: frags -> smem fp32 (reuse tile smem: 128*48*4 = 24576 <= 45056)
    __syncthreads();
    float* sout = reinterpret_cast<float*>(smem_raw);
#pragma unroll
    for (int nt = 0; nt < 3; nt++)
        wmma::store_matrix_sync(sout + (wid * 16) * G1_NPAD + nt * 16, acc[nt],
                                G1_NPAD, wmma::mem_row_major);
    __syncthreads();

    // write 40 used cols, coalesced: 5120 floats, 20 per thread
#pragma unroll
    for (int i = 0; i < 20; i++) {
        int idx = tid + i * 256;
        int r = idx / NHID;
        int c = idx - r * NHID;
        int gr = row0 + r;
        if (gr < N_NODES) g_support1[gr * NHID + c] = sout[r * G1_NPAD + c];
    }
}

// ---------------- zero both scatter targets ------------------------------------
__global__ void zero_kernel() {
    int i = blockIdx.x * blockDim.x + threadIdx.x;
    const int n1 = N_NODES * NHID / 4;
    const int n2 = N_NODES * NC_PAD / 4;
    if (i < n1)
        reinterpret_cast<float4*>(g_agg1)[i] = make_float4(0.f, 0.f, 0.f, 0.f);
    else if (i < n1 + n2)
        reinterpret_cast<float4*>(g_agg2)[i - n1] = make_float4(0.f, 0.f, 0.f, 0.f);
}

// ---------------- scatter 1: agg1[dst] += support1[src] * w  (40 wide) ---------
__global__ __launch_bounds__(256) void scatter1_kernel(const int* __restrict__ src,
                                                       const int* __restrict__ dst,
                                                       const float* __restrict__ ew) {
    int t = blockIdx.x * blockDim.x + threadIdx.x;
    if (t >= N_EDGES * 10) return;
    int e = t / 10;
    int c = t - e * 10;           // chunk 0..9
    int s = src[e];
    int d = dst[e];
    float w = ew[e];
    float4 v = reinterpret_cast<const float4*>(g_support1 + s * NHID)[c];
    v.x *= w; v.y *= w; v.z *= w; v.w *= w;
    red_add_v4(g_agg1 + d * NHID + c * 4, v);
}

// ---------------- layer-1 epilogue fused with GEMM2 ----------------------------
__global__ __launch_bounds__(256) void mid_kernel(const float* __restrict__ b1,
                                                  const float* __restrict__ W2,
                                                  const float* __restrict__ mask) {
    __shared__ float sW2[NHID][NCLASS];
    __shared__ float sb1[NHID];
    int tid = threadIdx.x;
    for (int i = tid; i < NHID * NCLASS; i += blockDim.x)
        sW2[i / NCLASS][i % NCLASS] = W2[i];
    if (tid < NHID) sb1[tid] = b1[tid];
    __syncthreads();

    int n = blockIdx.x * blockDim.x + tid;
    if (n >= N_NODES) return;

    float acc[NC_PAD];
#pragma unroll
    for (int c = 0; c < NC_PAD; c++) acc[c] = 0.f;

    const float4* arow = reinterpret_cast<const float4*>(g_agg1 + n * NHID);
    const float4* mrow = reinterpret_cast<const float4*>(mask + n * NHID);
#pragma unroll
    for (int q = 0; q < NHID / 4; q++) {
        float4 a = arow[q];
        float4 m = mrow[q];
        float hv[4];
        hv[0] = (m.x > 0.5f) ? fmaxf(a.x + sb1[4 * q + 0], 0.f) * 2.f : 0.f;
        hv[1] = (m.y > 0.5f) ? fmaxf(a.y + sb1[4 * q + 1], 0.f) * 2.f : 0.f;
        hv[2] = (m.z > 0.5f) ? fmaxf(a.z + sb1[4 * q + 2], 0.f) * 2.f : 0.f;
        hv[3] = (m.w > 0.5f) ? fmaxf(a.w + sb1[4 * q + 3], 0.f) * 2.f : 0.f;
#pragma unroll
        for (int u = 0; u < 4; u++) {
#pragma unroll
            for (int c = 0; c < NCLASS; c++) acc[c] += hv[u] * sW2[4 * q + u][c];
        }
    }
    float4* orow = reinterpret_cast<float4*>(g_support2 + n * NC_PAD);
    orow[0] = make_float4(acc[0], acc[1], acc[2], acc[3]);
    orow[1] = make_float4(acc[4], acc[5], acc[6], 0.f);
}

// ---------------- scatter 2: agg2[dst] += support2[src] * w  (8 wide padded) ---
__global__ __launch_bounds__(256) void scatter2_kernel(const int* __restrict__ src,
                                                       const int* __restrict__ dst,
                                                       const float* __restrict__ ew) {
    int t = blockIdx.x * blockDim.x + threadIdx.x;
    if (t >= N_EDGES * 2) return;
    int e = t >> 1;
    int c = t & 1;
    int s = src[e];
    int d = dst[e];
    float w = ew[e];
    float4 v = reinterpret_cast<const float4*>(g_support2 + s * NC_PAD)[c];
    v.x *= w; v.y *= w; v.z *= w; v.w *= w;
    red_add_v4(g_agg2 + d * NC_PAD + c * 4, v);
}

// ---------------- final: out = log_softmax(agg2 + b2) --------------------------
__global__ __launch_bounds__(256) void logsoftmax_kernel(const float* __restrict__ b2,
                                                         float* __restrict__ out) {
    int n = blockIdx.x * blockDim.x + threadIdx.x;
    if (n >= N_NODES) return;
    float v[NCLASS];
    float m = -1e30f;
#pragma unroll
    for (int c = 0; c < NCLASS; c++) {
        v[c] = g_agg2[n * NC_PAD + c] + b2[c];
        m = fmaxf(m, v[c]);
    }
    float sum = 0.f;
#pragma unroll
    for (int c = 0; c < NCLASS; c++) sum += expf(v[c] - m);
    float l = m + logf(sum);
#pragma unroll
    for (int c = 0; c < NCLASS; c++) out[n * NCLASS + c] = v[c] - l;
}

// ---------------- launch --------------------------------------------------------
extern "C" void kernel_launch(void* const* d_in, const int* in_sizes, int n_in,
                              void* d_out, int out_size) {
    const float* x    = (const float*)d_in[0];
    const int*   src  = (const int*)d_in[1];
    const int*   dst  = (const int*)d_in[2];
    const float* ew   = (const float*)d_in[3];
    const float* W1   = (const float*)d_in[4];
    const float* b1   = (const float*)d_in[5];
    const float* W2   = (const float*)d_in[6];
    const float* b2   = (const float*)d_in[7];
    const float* mask = (const float*)d_in[8];
    float* out = (float*)d_out;

    (void)in_sizes; (void)n_in; (void)out_size;

    // zero scatter targets (agg1 + agg2)
    {
        int total = N_NODES * NHID / 4 + N_NODES * NC_PAD / 4;
        zero_kernel<<<(total + 255) / 256, 256>>>();
    }

    // layer 1 dense on HMMA tensor cores (wmma bf16 split)
    gemm1_wmma_kernel<<<(N_NODES + G1_ROWS - 1) / G1_ROWS, 256>>>(x, W1);

    // layer 1 sparse aggregate: 10 v4-chunks per edge
    {
        long long total = (long long)N_EDGES * 10;
        int blocks = (int)((total + 255) / 256);
        scatter1_kernel<<<blocks, 256>>>(src, dst, ew);
    }

    // relu + bias + dropout + GEMM2 fused
    mid_kernel<<<(N_NODES + 255) / 256, 256>>>(b1, W2, mask);

    // layer 2 sparse aggregate: 2 v4-chunks per edge
    {
        long long total = (long long)N_EDGES * 2;
        int blocks = (int)((total + 255) / 256);
        scatter2_kernel<<<blocks, 256>>>(src, dst, ew);
    }

    // bias + log_softmax (reads padded agg2, writes 7-wide out)
    logsoftmax_kernel<<<(N_NODES + 255) / 256, 256>>>(b2, out);
}

// round 8
// speedup vs baseline: 1.0666x; 1.0666x over previous
#include <cuda_runtime.h>
#include <cuda_bf16.h>
#include <cstdint>
#include <mma.h>

using namespace nvcuda;

#define N_NODES 100000
#define N_EDGES 3200000
#define NFEAT 1433
#define NHID 40
#define NCLASS 7
#define NC_PAD 8   // padded class dim for vectorized reds

// ---------------- scratch (device globals; no allocations allowed) -------------
__device__ __align__(16) float g_support1[N_NODES * NHID];   // x @ W1
__device__ __align__(16) float g_agg1[N_NODES * NHID];       // scatter target 1
__device__ __align__(16) float g_support2[N_NODES * NC_PAD]; // h @ W2 (padded)
__device__ __align__(16) float g_agg2[N_NODES * NC_PAD];     // scatter target 2

// vector fp32 reduction (sm_90+): one RED.128 instead of 4 scalar REDs
__device__ __forceinline__ void red_add_v4(float* addr, float4 v) {
    asm volatile("red.global.add.v4.f32 [%0], {%1, %2, %3, %4};"
                 :: "l"(addr), "f"(v.x), "f"(v.y), "f"(v.z), "f"(v.w)
                 : "memory");
}

// ================== GEMM1 via wmma tf32 HMMA (single term) =====================
// support1[N,40] = x[N,1433] @ W1[1433,40]
// tf32 operands (11-bit mantissa), fp32 accumulate. No hi/lo split needed:
// expected rel err ~1e-4 << 1e-3 gate. Fill path is pure fp32 copies.
// Block: 256 thr (8 warps), tile 128 rows x 48 cols (40 used), KC=64.

#define G1_KC 64
#define G1_NPAD 48
#define G1_ROWS 128

__global__ __launch_bounds__(256) void gemm1_tf32_kernel(const float* __restrict__ x,
                                                         const float* __restrict__ W1) {
    __shared__ __align__(16) float sx[G1_ROWS * G1_KC];   // 32 KB
    __shared__ __align__(16) float sw[G1_KC * G1_NPAD];   // 12 KB

    const int tid = threadIdx.x;
    const int wid = tid >> 5;
    const int row0 = blockIdx.x * G1_ROWS;

    wmma::fragment<wmma::accumulator, 16, 16, 8, float> acc[3];
#pragma unroll
    for (int t = 0; t < 3; t++) wmma::fill_fragment(acc[t], 0.0f);

    for (int kb = 0; kb < NFEAT; kb += G1_KC) {
        __syncthreads();   // previous iteration's fragment reads done before refill

        // ---- x tile: 128 rows x 64 k, plain fp32 copy (coalesced within row)
#pragma unroll
        for (int i = 0; i < 32; i++) {
            int idx = tid + i * 256;
            int r = idx >> 6;
            int c = idx & 63;
            int gr = row0 + r;
            int gk = kb + c;
            sx[idx] = (gr < N_NODES && gk < NFEAT) ? __ldg(&x[(size_t)gr * NFEAT + gk]) : 0.f;
        }
        // ---- W tile: 64 k x 48 n (cols 40..47 zero), plain fp32 copy
#pragma unroll
        for (int i = 0; i < 12; i++) {
            int idx = tid + i * 256;
            int kk = idx / G1_NPAD;
            int nn = idx - kk * G1_NPAD;
            int gk = kb + kk;
            sw[idx] = (gk < NFEAT && nn < NHID) ? __ldg(&W1[gk * NHID + nn]) : 0.f;
        }
        __syncthreads();

#pragma unroll
        for (int ks = 0; ks < G1_KC / 8; ks++) {
            wmma::fragment<wmma::matrix_a, 16, 16, 8, wmma::precision::tf32, wmma::row_major> a;
            wmma::load_matrix_sync(a, sx + (wid * 16) * G1_KC + ks * 8, G1_KC);
#pragma unroll
            for (int t = 0; t < a.num_elements; t++) a.x[t] = wmma::__float_to_tf32(a.x[t]);
#pragma unroll
            for (int nt = 0; nt < 3; nt++) {
                wmma::fragment<wmma::matrix_b, 16, 16, 8, wmma::precision::tf32, wmma::row_major> b;
                wmma::load_matrix_sync(b, sw + (ks * 8) * G1_NPAD + nt * 16, G1_NPAD);
#pragma unroll
                for (int t = 0; t < b.num_elements; t++) b.x[t] = wmma::__float_to_tf32(b.x[t]);
                wmma::mma_sync(acc[nt], a, b, acc[nt]);
            }
        }
    }

    // epilogue: frags -> smem fp32 (reuse sx: 128*48*4 = 24576 <= 32768)
    __syncthreads();
    float* sout = sx;
#pragma unroll
    for (int nt = 0; nt < 3; nt++)
        wmma::store_matrix_sync(sout + (wid * 16) * G1_NPAD + nt * 16, acc[nt],
                                G1_NPAD, wmma::mem_row_major);
    __syncthreads();

    // write 40 used cols, coalesced: 5120 floats, 20 per thread
#pragma unroll
    for (int i = 0; i < 20; i++) {
        int idx = tid + i * 256;
        int r = idx / NHID;
        int c = idx - r * NHID;
        int gr = row0 + r;
        if (gr < N_NODES) g_support1[gr * NHID + c] = sout[r * G1_NPAD + c];
    }
}

// ---------------- zero both scatter targets ------------------------------------
__global__ void zero_kernel() {
    int i = blockIdx.x * blockDim.x + threadIdx.x;
    const int n1 = N_NODES * NHID / 4;
    const int n2 = N_NODES * NC_PAD / 4;
    if (i < n1)
        reinterpret_cast<float4*>(g_agg1)[i] = make_float4(0.f, 0.f, 0.f, 0.f);
    else if (i < n1 + n2)
        reinterpret_cast<float4*>(g_agg2)[i - n1] = make_float4(0.f, 0.f, 0.f, 0.f);
}

// ---------------- scatter 1: agg1[dst] += support1[src] * w  (40 wide) ---------
__global__ __launch_bounds__(256) void scatter1_kernel(const int* __restrict__ src,
                                                       const int* __restrict__ dst,
                                                       const float* __restrict__ ew) {
    int t = blockIdx.x * blockDim.x + threadIdx.x;
    if (t >= N_EDGES * 10) return;
    int e = t / 10;
    int c = t - e * 10;           // chunk 0..9
    int s = src[e];
    int d = dst[e];
    float w = ew[e];
    float4 v = reinterpret_cast<const float4*>(g_support1 + s * NHID)[c];
    v.x *= w; v.y *= w; v.z *= w; v.w *= w;
    red_add_v4(g_agg1 + d * NHID + c * 4, v);
}

// ---------------- layer-1 epilogue fused with GEMM2 ----------------------------
__global__ __launch_bounds__(256) void mid_kernel(const float* __restrict__ b1,
                                                  const float* __restrict__ W2,
                                                  const float* __restrict__ mask) {
    __shared__ float sW2[NHID][NCLASS];
    __shared__ float sb1[NHID];
    int tid = threadIdx.x;
    for (int i = tid; i < NHID * NCLASS; i += blockDim.x)
        sW2[i / NCLASS][i % NCLASS] = W2[i];
    if (tid < NHID) sb1[tid] = b1[tid];
    __syncthreads();

    int n = blockIdx.x * blockDim.x + tid;
    if (n >= N_NODES) return;

    float acc[NC_PAD];
#pragma unroll
    for (int c = 0; c < NC_PAD; c++) acc[c] = 0.f;

    const float4* arow = reinterpret_cast<const float4*>(g_agg1 + n * NHID);
    const float4* mrow = reinterpret_cast<const float4*>(mask + n * NHID);
#pragma unroll
    for (int q = 0; q < NHID / 4; q++) {
        float4 a = arow[q];
        float4 m = mrow[q];
        float hv[4];
        hv[0] = (m.x > 0.5f) ? fmaxf(a.x + sb1[4 * q + 0], 0.f) * 2.f : 0.f;
        hv[1] = (m.y > 0.5f) ? fmaxf(a.y + sb1[4 * q + 1], 0.f) * 2.f : 0.f;
        hv[2] = (m.z > 0.5f) ? fmaxf(a.z + sb1[4 * q + 2], 0.f) * 2.f : 0.f;
        hv[3] = (m.w > 0.5f) ? fmaxf(a.w + sb1[4 * q + 3], 0.f) * 2.f : 0.f;
#pragma unroll
        for (int u = 0; u < 4; u++) {
#pragma unroll
            for (int c = 0; c < NCLASS; c++) acc[c] += hv[u] * sW2[4 * q + u][c];
        }
    }
    float4* orow = reinterpret_cast<float4*>(g_support2 + n * NC_PAD);
    orow[0] = make_float4(acc[0], acc[1], acc[2], acc[3]);
    orow[1] = make_float4(acc[4], acc[5], acc[6], 0.f);
}

// ---------------- scatter 2: agg2[dst] += support2[src] * w  (8 wide padded) ---
__global__ __launch_bounds__(256) void scatter2_kernel(const int* __restrict__ src,
                                                       const int* __restrict__ dst,
                                                       const float* __restrict__ ew) {
    int t = blockIdx.x * blockDim.x + threadIdx.x;
    if (t >= N_EDGES * 2) return;
    int e = t >> 1;
    int c = t & 1;
    int s = src[e];
    int d = dst[e];
    float w = ew[e];
    float4 v = reinterpret_cast<const float4*>(g_support2 + s * NC_PAD)[c];
    v.x *= w; v.y *= w; v.z *= w; v.w *= w;
    red_add_v4(g_agg2 + d * NC_PAD + c * 4, v);
}

// ---------------- final: out = log_softmax(agg2 + b2) --------------------------
__global__ __launch_bounds__(256) void logsoftmax_kernel(const float* __restrict__ b2,
                                                         float* __restrict__ out) {
    int n = blockIdx.x * blockDim.x + threadIdx.x;
    if (n >= N_NODES) return;
    float v[NCLASS];
    float m = -1e30f;
#pragma unroll
    for (int c = 0; c < NCLASS; c++) {
        v[c] = g_agg2[n * NC_PAD + c] + b2[c];
        m = fmaxf(m, v[c]);
    }
    float sum = 0.f;
#pragma unroll
    for (int c = 0; c < NCLASS; c++) sum += expf(v[c] - m);
    float l = m + logf(sum);
#pragma unroll
    for (int c = 0; c < NCLASS; c++) out[n * NCLASS + c] = v[c] - l;
}

// ---------------- launch --------------------------------------------------------
extern "C" void kernel_launch(void* const* d_in, const int* in_sizes, int n_in,
                              void* d_out, int out_size) {
    const float* x    = (const float*)d_in[0];
    const int*   src  = (const int*)d_in[1];
    const int*   dst  = (const int*)d_in[2];
    const float* ew   = (const float*)d_in[3];
    const float* W1   = (const float*)d_in[4];
    const float* b1   = (const float*)d_in[5];
    const float* W2   = (const float*)d_in[6];
    const float* b2   = (const float*)d_in[7];
    const float* mask = (const float*)d_in[8];
    float* out = (float*)d_out;

    (void)in_sizes; (void)n_in; (void)out_size;

    // zero scatter targets (agg1 + agg2)
    {
        int total = N_NODES * NHID / 4 + N_NODES * NC_PAD / 4;
        zero_kernel<<<(total + 255) / 256, 256>>>();
    }

    // layer 1 dense on tf32 tensor cores
    gemm1_tf32_kernel<<<(N_NODES + G1_ROWS - 1) / G1_ROWS, 256>>>(x, W1);

    // layer 1 sparse aggregate: 10 v4-chunks per edge
    {
        long long total = (long long)N_EDGES * 10;
        int blocks = (int)((total + 255) / 256);
        scatter1_kernel<<<blocks, 256>>>(src, dst, ew);
    }

    // relu + bias + dropout + GEMM2 fused
    mid_kernel<<<(N_NODES + 255) / 256, 256>>>(b1, W2, mask);

    // layer 2 sparse aggregate: 2 v4-chunks per edge
    {
        long long total = (long long)N_EDGES * 2;
        int blocks = (int)((total + 255) / 256);
        scatter2_kernel<<<blocks, 256>>>(src, dst, ew);
    }

    // bias + log_softmax (reads padded agg2, writes 7-wide out)
    logsoftmax_kernel<<<(N_NODES + 255) / 256, 256>>>(b2, out);
}